// round 10
// baseline (speedup 1.0000x reference)
#include <cuda_runtime.h>
#include <math.h>

// Problem dims (fixed by setup_inputs)
#define MAXN 100000
#define MAXB 256
#define D2 50
#define D3 15
#define D5 10
#define NC 6

// ---------------- device scratch ----------------
// per-node record: 15 accum floats + count in slot 15 (16 floats = 64B)
__device__ __align__(16) float g_x2sum[MAXN * 16];

// ---------------- packed f32x2 helpers ----------------
__device__ __forceinline__ unsigned long long pack2(float a, float b) {
    unsigned long long r;
    asm("mov.b64 %0, {%1, %2};" : "=l"(r) : "f"(a), "f"(b));
    return r;
}
__device__ __forceinline__ void unpack2(unsigned long long v, float& a, float& b) {
    asm("mov.b64 {%0, %1}, %2;" : "=f"(a), "=f"(b) : "l"(v));
}
__device__ __forceinline__ void ffma2(unsigned long long& acc,
                                      unsigned long long a, unsigned long long b) {
    asm("fma.rn.f32x2 %0, %1, %2, %0;" : "+l"(acc) : "l"(a), "l"(b));
}
__device__ __forceinline__ void red4(float* p, float a, float b, float c, float d) {
    asm volatile("red.global.add.v4.f32 [%0], {%1, %2, %3, %4};"
                 :: "l"(p), "f"(a), "f"(b), "f"(c), "f"(d) : "memory");
}

// ---------------- zero accumulators ----------------
__global__ void zero_kernel(int N) {
    int tid = blockIdx.x * blockDim.x + threadIdx.x;
    int stride = gridDim.x * blockDim.x;
    int total = N * 4;  // float4 units
    float4 z = make_float4(0.f, 0.f, 0.f, 0.f);
    float4* p = reinterpret_cast<float4*>(g_x2sum);
    for (int t = tid; t < total; t += stride) p[t] = z;
}

// ---------------- SMEM weight layout (floats) -----------------------------
// Layer-1 weights chunk-major:  [13 chunks][in][4 j]   (j = ch*4 + jl, pad 52)
// Layer-1 bias:                 [52] linear (j index)
// Layer-2 weights k-pair-major: [52 j][16 k]  (float t = j*16 + k, pad)
// Layer-2 bias:                 [16] linear (k index)
#define OFF_EW1   0                      // 13*9*4  = 468
#define OFF_EB1   468                    // 52
#define OFF_EW2KP 520                    // 52*16   = 832
#define OFF_EB2   1352                   // 16
#define OFF_NW1   1368                   // 13*18*4 = 936
#define OFF_NB1   2304                   // 52
#define OFF_NW2KP 2356                   // 832
#define OFF_NB2   3188                   // 16
#define SW_TOTAL  3204

// ---------------- edge kernel: 4 edges/thread, e2 in lane-indexed smem ----
__global__ void __launch_bounds__(128)
edge_kernel(
    const float* __restrict__ x,
    const int* __restrict__ row,
    const int* __restrict__ col,
    const float* __restrict__ ea,
    const float* __restrict__ ew1, const float* __restrict__ eb1,
    const float* __restrict__ ew2, const float* __restrict__ eb2,
    const float* __restrict__ nw1, const float* __restrict__ nb1,
    const float* __restrict__ nw2, const float* __restrict__ nb2,
    int P, int E)
{
    __shared__ __align__(16) float sw[SW_TOTAL];
    __shared__ float se2[15 * 4 * 128];   // e2 scratch: [k][e][tid], bank-clean

    // ---- stage weights (remapped layouts) ----
    for (int t = threadIdx.x; t < 13 * 9 * 4; t += blockDim.x) {
        int ch = t / 36, rem = t % 36, i = rem / 4, jl = rem % 4;
        int j = ch * 4 + jl;
        sw[OFF_EW1 + t] = (j < D2) ? ew1[i * D2 + j] : 0.0f;
    }
    for (int t = threadIdx.x; t < 52; t += blockDim.x)
        sw[OFF_EB1 + t] = (t < D2) ? eb1[t] : 0.0f;
    for (int t = threadIdx.x; t < 52 * 16; t += blockDim.x) {
        int j = t / 16, k = t % 16;
        sw[OFF_EW2KP + t] = (j < D2 && k < D3) ? ew2[j * D3 + k] : 0.0f;
    }
    for (int t = threadIdx.x; t < 16; t += blockDim.x)
        sw[OFF_EB2 + t] = (t < D3) ? eb2[t] : 0.0f;
    for (int t = threadIdx.x; t < 13 * 18 * 4; t += blockDim.x) {
        int ch = t / 72, rem = t % 72, i = rem / 4, jl = rem % 4;
        int j = ch * 4 + jl;
        sw[OFF_NW1 + t] = (j < D2) ? nw1[i * D2 + j] : 0.0f;
    }
    for (int t = threadIdx.x; t < 52; t += blockDim.x)
        sw[OFF_NB1 + t] = (t < D2) ? nb1[t] : 0.0f;
    for (int t = threadIdx.x; t < 52 * 16; t += blockDim.x) {
        int j = t / 16, k = t % 16;
        sw[OFF_NW2KP + t] = (j < D2 && k < D3) ? nw2[j * D3 + k] : 0.0f;
    }
    for (int t = threadIdx.x; t < 16; t += blockDim.x)
        sw[OFF_NB2 + t] = (t < D3) ? nb2[t] : 0.0f;
    __syncthreads();

    int tid = threadIdx.x;
    int p = blockIdx.x * blockDim.x + tid;
    if (p >= P) return;

    int e0 = 4 * p;
    bool full = (e0 + 3 < E);

    // ---- gather indices + inputs for 4 edges ----
    int r[4], c[4];
    float in9[4][9];
    if (full) {
        int4 rr = *reinterpret_cast<const int4*>(row + e0);
        int4 cc = *reinterpret_cast<const int4*>(col + e0);
        r[0] = rr.x; r[1] = rr.y; r[2] = rr.z; r[3] = rr.w;
        c[0] = cc.x; c[1] = cc.y; c[2] = cc.z; c[3] = cc.w;
        const float4* ea4 = reinterpret_cast<const float4*>(ea + 3 * e0);
        float4 a0 = ea4[0], a1 = ea4[1], a2 = ea4[2];
        in9[0][6] = a0.x; in9[0][7] = a0.y; in9[0][8] = a0.z;
        in9[1][6] = a0.w; in9[1][7] = a1.x; in9[1][8] = a1.y;
        in9[2][6] = a1.z; in9[2][7] = a1.w; in9[2][8] = a2.x;
        in9[3][6] = a2.y; in9[3][7] = a2.z; in9[3][8] = a2.w;
    } else {
        #pragma unroll
        for (int e = 0; e < 4; ++e) {
            int idx = min(e0 + e, E - 1);
            r[e] = row[idx]; c[e] = col[idx];
            in9[e][6] = ea[3 * idx + 0];
            in9[e][7] = ea[3 * idx + 1];
            in9[e][8] = ea[3 * idx + 2];
        }
    }
    #pragma unroll
    for (int e = 0; e < 4; ++e) {
        in9[e][0] = x[3 * r[e] + 0];
        in9[e][1] = x[3 * r[e] + 1];
        in9[e][2] = x[3 * r[e] + 2];
        in9[e][3] = x[3 * c[e] + 0];
        in9[e][4] = x[3 * c[e] + 1];
        in9[e][5] = x[3 * c[e] + 2];
    }

    // ================= EDGE MLP (fused layers) =================
    unsigned long long e2p[4][8];
    {
        const ulonglong2* bv = reinterpret_cast<const ulonglong2*>(&sw[OFF_EB2]);
        #pragma unroll
        for (int q = 0; q < 4; ++q) {
            ulonglong2 b = bv[q];
            #pragma unroll
            for (int e = 0; e < 4; ++e) {
                e2p[e][2 * q + 0] = b.x;
                e2p[e][2 * q + 1] = b.y;
            }
        }
    }
    #pragma unroll
    for (int ch = 0; ch < 13; ++ch) {
        unsigned long long h[4][2];
        {
            ulonglong2 b = *reinterpret_cast<const ulonglong2*>(&sw[OFF_EB1 + 4 * ch]);
            #pragma unroll
            for (int e = 0; e < 4; ++e) { h[e][0] = b.x; h[e][1] = b.y; }
        }
        #pragma unroll
        for (int i = 0; i < 9; ++i) {
            ulonglong2 w = *reinterpret_cast<const ulonglong2*>(
                &sw[OFF_EW1 + (ch * 9 + i) * 4]);
            #pragma unroll
            for (int e = 0; e < 4; ++e) {
                unsigned long long pa = pack2(in9[e][i], in9[e][i]);
                ffma2(h[e][0], pa, w.x);
                ffma2(h[e][1], pa, w.y);
            }
        }
        #pragma unroll
        for (int e = 0; e < 4; ++e) {
            float a, b;
            unpack2(h[e][0], a, b); h[e][0] = pack2(fmaxf(a, 0.f), fmaxf(b, 0.f));
            unpack2(h[e][1], a, b); h[e][1] = pack2(fmaxf(a, 0.f), fmaxf(b, 0.f));
        }
        #pragma unroll
        for (int jl = 0; jl < 4; ++jl) {
            int j = ch * 4 + jl;
            const ulonglong2* wp = reinterpret_cast<const ulonglong2*>(
                &sw[OFF_EW2KP + j * 16]);
            ulonglong2 w01 = wp[0], w23 = wp[1], w45 = wp[2], w67 = wp[3];
            #pragma unroll
            for (int e = 0; e < 4; ++e) {
                float a, b;
                unpack2(h[e][jl >> 1], a, b);
                float hj = (jl & 1) ? b : a;
                unsigned long long pj = pack2(hj, hj);
                ffma2(e2p[e][0], pj, w01.x);
                ffma2(e2p[e][1], pj, w01.y);
                ffma2(e2p[e][2], pj, w23.x);
                ffma2(e2p[e][3], pj, w23.y);
                ffma2(e2p[e][4], pj, w45.x);
                ffma2(e2p[e][5], pj, w45.y);
                ffma2(e2p[e][6], pj, w67.x);
                ffma2(e2p[e][7], pj, w67.y);
            }
        }
    }
    // fold e2 partials into lane-indexed shared scratch (frees ~60 regs)
    #pragma unroll
    for (int e = 0; e < 4; ++e) {
        #pragma unroll
        for (int kp = 0; kp < 8; ++kp) {
            float lo, hi;
            unpack2(e2p[e][kp], lo, hi);
            int k0 = 2 * kp, k1 = 2 * kp + 1;
            if (k0 < 15) se2[(k0 * 4 + e) * 128 + tid] = lo;
            if (k1 < 15) se2[(k1 * 4 + e) * 128 + tid] = hi;
        }
    }

    // ================= NODE MLP (fused layers) =================
    unsigned long long op[4][8];
    {
        const ulonglong2* bv = reinterpret_cast<const ulonglong2*>(&sw[OFF_NB2]);
        #pragma unroll
        for (int q = 0; q < 4; ++q) {
            ulonglong2 b = bv[q];
            #pragma unroll
            for (int e = 0; e < 4; ++e) {
                op[e][2 * q + 0] = b.x;
                op[e][2 * q + 1] = b.y;
            }
        }
    }
    #pragma unroll
    for (int ch = 0; ch < 13; ++ch) {
        unsigned long long h2[4][2];
        {
            ulonglong2 b = *reinterpret_cast<const ulonglong2*>(&sw[OFF_NB1 + 4 * ch]);
            #pragma unroll
            for (int e = 0; e < 4; ++e) { h2[e][0] = b.x; h2[e][1] = b.y; }
        }
        #pragma unroll
        for (int i = 0; i < 18; ++i) {
            ulonglong2 w = *reinterpret_cast<const ulonglong2*>(
                &sw[OFF_NW1 + (ch * 18 + i) * 4]);
            #pragma unroll
            for (int e = 0; e < 4; ++e) {
                float xi = (i < 3) ? in9[e][3 + i]
                                   : se2[((i - 3) * 4 + e) * 128 + tid];
                unsigned long long pa = pack2(xi, xi);
                ffma2(h2[e][0], pa, w.x);
                ffma2(h2[e][1], pa, w.y);
            }
        }
        #pragma unroll
        for (int e = 0; e < 4; ++e) {
            float a, b;
            unpack2(h2[e][0], a, b); h2[e][0] = pack2(fmaxf(a, 0.f), fmaxf(b, 0.f));
            unpack2(h2[e][1], a, b); h2[e][1] = pack2(fmaxf(a, 0.f), fmaxf(b, 0.f));
        }
        #pragma unroll
        for (int jl = 0; jl < 4; ++jl) {
            int j = ch * 4 + jl;
            const ulonglong2* wp = reinterpret_cast<const ulonglong2*>(
                &sw[OFF_NW2KP + j * 16]);
            ulonglong2 w01 = wp[0], w23 = wp[1], w45 = wp[2], w67 = wp[3];
            #pragma unroll
            for (int e = 0; e < 4; ++e) {
                float a, b;
                unpack2(h2[e][jl >> 1], a, b);
                float hj = (jl & 1) ? b : a;
                unsigned long long pj = pack2(hj, hj);
                ffma2(op[e][0], pj, w01.x);
                ffma2(op[e][1], pj, w01.y);
                ffma2(op[e][2], pj, w23.x);
                ffma2(op[e][3], pj, w23.y);
                ffma2(op[e][4], pj, w45.x);
                ffma2(op[e][5], pj, w45.y);
                ffma2(op[e][6], pj, w67.x);
                ffma2(op[e][7], pj, w67.y);
            }
        }
    }

    // ---- fold + scatter (slot 15 carries the count 1.0) ----
    #pragma unroll
    for (int e = 0; e < 4; ++e) {
        if (!full && (e0 + e >= E)) break;
        float o[16];
        #pragma unroll
        for (int kp = 0; kp < 8; ++kp)
            unpack2(op[e][kp], o[2 * kp], o[2 * kp + 1]);
        o[15] = 1.0f;
        float* dst = &g_x2sum[(size_t)r[e] * 16];
        red4(dst + 0,  o[0],  o[1],  o[2],  o[3]);
        red4(dst + 4,  o[4],  o[5],  o[6],  o[7]);
        red4(dst + 8,  o[8],  o[9],  o[10], o[11]);
        red4(dst + 12, o[12], o[13], o[14], o[15]);
    }
}

// ---------------- graph kernel: per-graph reduce + global MLP + head -------
#define SG_GW1 0
#define SG_GB1 (SG_GW1 + 16 * D2)
#define SG_GW2 (SG_GB1 + D2)
#define SG_GB2 (SG_GW2 + D2 * D3)
#define SG_F1W (SG_GB2 + D3)
#define SG_F1B (SG_F1W + D3 * D5)
#define SG_BNG (SG_F1B + D5)
#define SG_BNB (SG_BNG + D5)
#define SG_F2W (SG_BNB + D5)
#define SG_F2B (SG_F2W + D5 * NC)
#define SG_TOTAL (SG_F2B + NC)

__device__ __forceinline__ int lbound(const int* a, int n, int key) {
    int lo = 0, hi = n;
    while (lo < hi) { int m = (lo + hi) >> 1; if (a[m] < key) lo = m + 1; else hi = m; }
    return lo;
}

__global__ void __launch_bounds__(256)
graph_kernel(
    const int* __restrict__ batch,
    const float* __restrict__ u,
    const float* __restrict__ gw1, const float* __restrict__ gb1,
    const float* __restrict__ gw2, const float* __restrict__ gb2,
    const float* __restrict__ fc1w, const float* __restrict__ fc1b,
    const float* __restrict__ bng, const float* __restrict__ bnb,
    const float* __restrict__ fc2w, const float* __restrict__ fc2b,
    float* __restrict__ out, int N)
{
    __shared__ float swt[SG_TOTAL];
    __shared__ float sred[8][30];
    __shared__ int sse[2];

    int tid = threadIdx.x;
    for (int t = tid; t < 16 * D2; t += blockDim.x) swt[SG_GW1 + t] = gw1[t];
    for (int t = tid; t < D2; t += blockDim.x) swt[SG_GB1 + t] = gb1[t];
    for (int t = tid; t < D2 * D3; t += blockDim.x) swt[SG_GW2 + t] = gw2[t];
    for (int t = tid; t < D3; t += blockDim.x) swt[SG_GB2 + t] = gb2[t];
    for (int t = tid; t < D3 * D5; t += blockDim.x) swt[SG_F1W + t] = fc1w[t];
    for (int t = tid; t < D5; t += blockDim.x) {
        swt[SG_F1B + t] = fc1b[t];
        swt[SG_BNG + t] = bng[t];
        swt[SG_BNB + t] = bnb[t];
    }
    for (int t = tid; t < D5 * NC; t += blockDim.x) swt[SG_F2W + t] = fc2w[t];
    for (int t = tid; t < NC; t += blockDim.x) swt[SG_F2B + t] = fc2b[t];

    int b = blockIdx.x;
    if (tid == 0) {
        sse[0] = lbound(batch, N, b);
        sse[1] = lbound(batch, N, b + 1);
    }
    __syncthreads();
    int s = sse[0], epos = sse[1];
    int nnodes = epos - s;

    float acc[30];
    #pragma unroll
    for (int k = 0; k < 30; ++k) acc[k] = 0.0f;

    for (int n = s + tid; n < epos; n += blockDim.x) {
        const float4* p = reinterpret_cast<const float4*>(&g_x2sum[(size_t)n * 16]);
        float4 a0 = p[0], a1 = p[1], a2 = p[2], a3 = p[3];
        float vv[15] = { a0.x, a0.y, a0.z, a0.w, a1.x, a1.y, a1.z, a1.w,
                         a2.x, a2.y, a2.z, a2.w, a3.x, a3.y, a3.z };
        float cnt = a3.w;
        float inv = 1.0f / fmaxf(cnt, 1.0f);
        #pragma unroll
        for (int k = 0; k < 15; ++k) {
            float t = vv[k] * inv;
            acc[k] += t;
            acc[15 + k] += fmaxf(t, 0.0f);
        }
    }

    #pragma unroll
    for (int k = 0; k < 30; ++k) {
        float v = acc[k];
        #pragma unroll
        for (int off = 16; off > 0; off >>= 1)
            v += __shfl_down_sync(0xFFFFFFFF, v, off);
        acc[k] = v;
    }
    int wid = tid >> 5, lid = tid & 31;
    if (lid == 0) {
        #pragma unroll
        for (int k = 0; k < 30; ++k) sred[wid][k] = acc[k];
    }
    __syncthreads();

    if (tid == 0) {
        float gsum[15], zsum[15];
        #pragma unroll
        for (int k = 0; k < 15; ++k) { gsum[k] = 0.0f; zsum[k] = 0.0f; }
        for (int w = 0; w < (int)(blockDim.x >> 5); ++w) {
            #pragma unroll
            for (int k = 0; k < 15; ++k) {
                gsum[k] += sred[w][k];
                zsum[k] += sred[w][15 + k];
            }
        }

        float cntf = (float)nnodes;
        float invc = 1.0f / fmaxf(cntf, 1.0f);

        float in16[16];
        in16[0] = u[b];
        #pragma unroll
        for (int k = 0; k < 15; ++k) in16[1 + k] = gsum[k] * invc;

        float hg[D2];
        #pragma unroll
        for (int j = 0; j < D2; ++j) hg[j] = swt[SG_GB1 + j];
        #pragma unroll
        for (int i = 0; i < 16; ++i) {
            float xi = in16[i];
            #pragma unroll
            for (int j = 0; j < D2; ++j) hg[j] += xi * swt[SG_GW1 + i * D2 + j];
        }
        #pragma unroll
        for (int j = 0; j < D2; ++j) hg[j] = fmaxf(hg[j], 0.0f);

        float u2[D3];
        #pragma unroll
        for (int k = 0; k < D3; ++k) u2[k] = swt[SG_GB2 + k];
        #pragma unroll
        for (int j = 0; j < D2; ++j) {
            float hj = hg[j];
            #pragma unroll
            for (int k = 0; k < D3; ++k) u2[k] += hj * swt[SG_GW2 + j * D3 + k];
        }

        float invg = 1.0f / (cntf + 1.0f);
        float g[D3];
        #pragma unroll
        for (int k = 0; k < D3; ++k)
            g[k] = (zsum[k] + fmaxf(u2[k], 0.0f)) * invg;

        float h1[D5];
        #pragma unroll
        for (int m = 0; m < D5; ++m) h1[m] = swt[SG_F1B + m];
        #pragma unroll
        for (int k = 0; k < D3; ++k) {
            float gk = g[k];
            #pragma unroll
            for (int m = 0; m < D5; ++m) h1[m] += gk * swt[SG_F1W + k * D5 + m];
        }

        float rs = rsqrtf(1.0f + 1e-5f);
        #pragma unroll
        for (int m = 0; m < D5; ++m)
            h1[m] = fmaxf(h1[m] * (swt[SG_BNG + m] * rs) + swt[SG_BNB + m], 0.0f);

        float lg[NC];
        #pragma unroll
        for (int q = 0; q < NC; ++q) lg[q] = swt[SG_F2B + q];
        #pragma unroll
        for (int m = 0; m < D5; ++m) {
            float hm = h1[m];
            #pragma unroll
            for (int q = 0; q < NC; ++q) lg[q] += hm * swt[SG_F2W + m * NC + q];
        }

        float mx = lg[0];
        #pragma unroll
        for (int q = 1; q < NC; ++q) mx = fmaxf(mx, lg[q]);
        float ssum = 0.0f;
        #pragma unroll
        for (int q = 0; q < NC; ++q) ssum += expf(lg[q] - mx);
        float lse = mx + logf(ssum);
        #pragma unroll
        for (int q = 0; q < NC; ++q) out[b * NC + q] = lg[q] - lse;
    }
}

// ---------------- launch ----------------
extern "C" void kernel_launch(void* const* d_in, const int* in_sizes, int n_in,
                              void* d_out, int out_size) {
    const float* x     = (const float*)d_in[0];
    const int*   ei    = (const int*)d_in[1];
    const float* ea    = (const float*)d_in[2];
    const float* u     = (const float*)d_in[3];
    const int*   batch = (const int*)d_in[4];
    const float* ew1   = (const float*)d_in[5];
    const float* eb1   = (const float*)d_in[6];
    const float* ew2   = (const float*)d_in[7];
    const float* eb2   = (const float*)d_in[8];
    const float* nw1   = (const float*)d_in[9];
    const float* nb1   = (const float*)d_in[10];
    const float* nw2   = (const float*)d_in[11];
    const float* nb2   = (const float*)d_in[12];
    const float* gw1   = (const float*)d_in[13];
    const float* gb1   = (const float*)d_in[14];
    const float* gw2   = (const float*)d_in[15];
    const float* gb2   = (const float*)d_in[16];
    const float* fc1w  = (const float*)d_in[17];
    const float* fc1b  = (const float*)d_in[18];
    const float* bng   = (const float*)d_in[19];
    const float* bnb   = (const float*)d_in[20];
    const float* fc2w  = (const float*)d_in[21];
    const float* fc2b  = (const float*)d_in[22];
    float* out = (float*)d_out;

    int N = in_sizes[0] / 3;   // nodes
    int E = in_sizes[1] / 2;   // edges
    int B = in_sizes[3];       // graphs

    const int* row = ei;
    const int* col = ei + E;

    zero_kernel<<<512, 256>>>(N);

    int P = (E + 3) / 4;       // 4 edges per thread
    edge_kernel<<<(P + 127) / 128, 128>>>(x, row, col, ea,
                                          ew1, eb1, ew2, eb2,
                                          nw1, nb1, nw2, nb2, P, E);

    graph_kernel<<<B, 256>>>(batch, u,
                             gw1, gb1, gw2, gb2,
                             fc1w, fc1b, bng, bnb, fc2w, fc2b, out, N);
}

// round 11
// speedup vs baseline: 1.0191x; 1.0191x over previous
#include <cuda_runtime.h>
#include <math.h>

// Problem dims (fixed by setup_inputs)
#define MAXN 100000
#define MAXB 256
#define D2 50
#define D3 15
#define D5 10
#define NC 6

// ---------------- device scratch ----------------
// per-node record: 15 accum floats + count in slot 15 (16 floats = 64B)
__device__ __align__(16) float g_x2sum[MAXN * 16];

// ---------------- packed f32x2 helpers ----------------
__device__ __forceinline__ unsigned long long pack2(float a, float b) {
    unsigned long long r;
    asm("mov.b64 %0, {%1, %2};" : "=l"(r) : "f"(a), "f"(b));
    return r;
}
__device__ __forceinline__ void unpack2(unsigned long long v, float& a, float& b) {
    asm("mov.b64 {%0, %1}, %2;" : "=f"(a), "=f"(b) : "l"(v));
}
__device__ __forceinline__ void ffma2(unsigned long long& acc,
                                      unsigned long long a, unsigned long long b) {
    asm("fma.rn.f32x2 %0, %1, %2, %0;" : "+l"(acc) : "l"(a), "l"(b));
}
__device__ __forceinline__ void red4(float* p, float a, float b, float c, float d) {
    asm volatile("red.global.add.v4.f32 [%0], {%1, %2, %3, %4};"
                 :: "l"(p), "f"(a), "f"(b), "f"(c), "f"(d) : "memory");
}

// ---------------- zero accumulators ----------------
__global__ void zero_kernel(int N) {
    int tid = blockIdx.x * blockDim.x + threadIdx.x;
    int stride = gridDim.x * blockDim.x;
    int total = N * 4;  // float4 units
    float4 z = make_float4(0.f, 0.f, 0.f, 0.f);
    float4* p = reinterpret_cast<float4*>(g_x2sum);
    for (int t = tid; t < total; t += stride) p[t] = z;
}

// ---------------- SMEM weight layout (floats) -----------------------------
// Layer-1 weights chunk-major:  [13 chunks][in][4 j]   (j = ch*4 + jl, pad 52)
// Layer-1 bias:                 [52] linear (j index)
// Layer-2 weights k-pair-major: [52 j][16 k]  (float t = j*16 + k, pad)
// Layer-2 bias:                 [16] linear (k index)
#define OFF_EW1   0                      // 13*9*4  = 468
#define OFF_EB1   468                    // 52
#define OFF_EW2KP 520                    // 52*16   = 832
#define OFF_EB2   1352                   // 16
#define OFF_NW1   1368                   // 13*18*4 = 936
#define OFF_NB1   2304                   // 52
#define OFF_NW2KP 2356                   // 832
#define OFF_NB2   3188                   // 16
#define SW_TOTAL  3204

// ---------------- edge kernel: 2 edges/thread, fused chunk consumption ----
__global__ void __launch_bounds__(128)
edge_kernel(
    const float* __restrict__ x,
    const int* __restrict__ row,
    const int* __restrict__ col,
    const float* __restrict__ ea,
    const float* __restrict__ ew1, const float* __restrict__ eb1,
    const float* __restrict__ ew2, const float* __restrict__ eb2,
    const float* __restrict__ nw1, const float* __restrict__ nb1,
    const float* __restrict__ nw2, const float* __restrict__ nb2,
    int P, int E)
{
    __shared__ __align__(16) float sw[SW_TOTAL];

    // ---- stage weights (remapped layouts) ----
    for (int t = threadIdx.x; t < 13 * 9 * 4; t += blockDim.x) {
        int ch = t / 36, rem = t % 36, i = rem / 4, jl = rem % 4;
        int j = ch * 4 + jl;
        sw[OFF_EW1 + t] = (j < D2) ? ew1[i * D2 + j] : 0.0f;
    }
    for (int t = threadIdx.x; t < 52; t += blockDim.x)
        sw[OFF_EB1 + t] = (t < D2) ? eb1[t] : 0.0f;
    for (int t = threadIdx.x; t < 52 * 16; t += blockDim.x) {
        int j = t / 16, k = t % 16;
        sw[OFF_EW2KP + t] = (j < D2 && k < D3) ? ew2[j * D3 + k] : 0.0f;
    }
    for (int t = threadIdx.x; t < 16; t += blockDim.x)
        sw[OFF_EB2 + t] = (t < D3) ? eb2[t] : 0.0f;
    for (int t = threadIdx.x; t < 13 * 18 * 4; t += blockDim.x) {
        int ch = t / 72, rem = t % 72, i = rem / 4, jl = rem % 4;
        int j = ch * 4 + jl;
        sw[OFF_NW1 + t] = (j < D2) ? nw1[i * D2 + j] : 0.0f;
    }
    for (int t = threadIdx.x; t < 52; t += blockDim.x)
        sw[OFF_NB1 + t] = (t < D2) ? nb1[t] : 0.0f;
    for (int t = threadIdx.x; t < 52 * 16; t += blockDim.x) {
        int j = t / 16, k = t % 16;
        sw[OFF_NW2KP + t] = (j < D2 && k < D3) ? nw2[j * D3 + k] : 0.0f;
    }
    for (int t = threadIdx.x; t < 16; t += blockDim.x)
        sw[OFF_NB2 + t] = (t < D3) ? nb2[t] : 0.0f;
    __syncthreads();

    int p = blockIdx.x * blockDim.x + threadIdx.x;
    if (p >= P) return;

    int e0 = 2 * p;
    bool full = (e0 + 1 < E);

    // ---- gather indices + inputs for 2 edges ----
    int r[2], c[2];
    float in9[2][9];
    if (full) {
        int2 rr = *reinterpret_cast<const int2*>(row + e0);
        int2 cc = *reinterpret_cast<const int2*>(col + e0);
        r[0] = rr.x; r[1] = rr.y;
        c[0] = cc.x; c[1] = cc.y;
        const float2* ea2 = reinterpret_cast<const float2*>(ea + 3 * e0);
        float2 a0 = ea2[0], a1 = ea2[1], a2 = ea2[2];
        in9[0][6] = a0.x; in9[0][7] = a0.y; in9[0][8] = a1.x;
        in9[1][6] = a1.y; in9[1][7] = a2.x; in9[1][8] = a2.y;
    } else {
        int idx = E - 1;
        r[0] = row[idx]; c[0] = col[idx];
        in9[0][6] = ea[3 * idx + 0];
        in9[0][7] = ea[3 * idx + 1];
        in9[0][8] = ea[3 * idx + 2];
        r[1] = r[0]; c[1] = c[0];
        in9[1][6] = in9[0][6]; in9[1][7] = in9[0][7]; in9[1][8] = in9[0][8];
    }
    #pragma unroll
    for (int e = 0; e < 2; ++e) {
        in9[e][0] = x[3 * r[e] + 0];
        in9[e][1] = x[3 * r[e] + 1];
        in9[e][2] = x[3 * r[e] + 2];
        in9[e][3] = x[3 * c[e] + 0];
        in9[e][4] = x[3 * c[e] + 1];
        in9[e][5] = x[3 * c[e] + 2];
    }

    // ================= EDGE MLP (fused layers) =================
    unsigned long long e2p[2][8];
    {
        const ulonglong2* bv = reinterpret_cast<const ulonglong2*>(&sw[OFF_EB2]);
        #pragma unroll
        for (int q = 0; q < 4; ++q) {
            ulonglong2 b = bv[q];
            #pragma unroll
            for (int e = 0; e < 2; ++e) {
                e2p[e][2 * q + 0] = b.x;
                e2p[e][2 * q + 1] = b.y;
            }
        }
    }
    #pragma unroll
    for (int ch = 0; ch < 13; ++ch) {
        unsigned long long h[2][2];
        {
            ulonglong2 b = *reinterpret_cast<const ulonglong2*>(&sw[OFF_EB1 + 4 * ch]);
            #pragma unroll
            for (int e = 0; e < 2; ++e) { h[e][0] = b.x; h[e][1] = b.y; }
        }
        #pragma unroll
        for (int i = 0; i < 9; ++i) {
            ulonglong2 w = *reinterpret_cast<const ulonglong2*>(
                &sw[OFF_EW1 + (ch * 9 + i) * 4]);
            #pragma unroll
            for (int e = 0; e < 2; ++e) {
                unsigned long long pa = pack2(in9[e][i], in9[e][i]);
                ffma2(h[e][0], pa, w.x);
                ffma2(h[e][1], pa, w.y);
            }
        }
        #pragma unroll
        for (int e = 0; e < 2; ++e) {
            float a, b;
            unpack2(h[e][0], a, b); h[e][0] = pack2(fmaxf(a, 0.f), fmaxf(b, 0.f));
            unpack2(h[e][1], a, b); h[e][1] = pack2(fmaxf(a, 0.f), fmaxf(b, 0.f));
        }
        #pragma unroll
        for (int jl = 0; jl < 4; ++jl) {
            int j = ch * 4 + jl;
            const ulonglong2* wp = reinterpret_cast<const ulonglong2*>(
                &sw[OFF_EW2KP + j * 16]);
            ulonglong2 w01 = wp[0], w23 = wp[1], w45 = wp[2], w67 = wp[3];
            #pragma unroll
            for (int e = 0; e < 2; ++e) {
                float a, b;
                unpack2(h[e][jl >> 1], a, b);
                float hj = (jl & 1) ? b : a;
                unsigned long long pj = pack2(hj, hj);
                ffma2(e2p[e][0], pj, w01.x);
                ffma2(e2p[e][1], pj, w01.y);
                ffma2(e2p[e][2], pj, w23.x);
                ffma2(e2p[e][3], pj, w23.y);
                ffma2(e2p[e][4], pj, w45.x);
                ffma2(e2p[e][5], pj, w45.y);
                ffma2(e2p[e][6], pj, w67.x);
                ffma2(e2p[e][7], pj, w67.y);
            }
        }
    }
    // fold e2 partials to scalars (bias already in)
    float e2f[2][15];
    #pragma unroll
    for (int e = 0; e < 2; ++e) {
        #pragma unroll
        for (int kp = 0; kp < 8; ++kp) {
            float lo, hi;
            unpack2(e2p[e][kp], lo, hi);
            if (2 * kp < 15)     e2f[e][2 * kp] = lo;
            if (2 * kp + 1 < 15) e2f[e][2 * kp + 1] = hi;
        }
    }

    // ================= NODE MLP (fused layers) =================
    unsigned long long op[2][8];
    {
        const ulonglong2* bv = reinterpret_cast<const ulonglong2*>(&sw[OFF_NB2]);
        #pragma unroll
        for (int q = 0; q < 4; ++q) {
            ulonglong2 b = bv[q];
            #pragma unroll
            for (int e = 0; e < 2; ++e) {
                op[e][2 * q + 0] = b.x;
                op[e][2 * q + 1] = b.y;
            }
        }
    }
    #pragma unroll
    for (int ch = 0; ch < 13; ++ch) {
        unsigned long long h2[2][2];
        {
            ulonglong2 b = *reinterpret_cast<const ulonglong2*>(&sw[OFF_NB1 + 4 * ch]);
            #pragma unroll
            for (int e = 0; e < 2; ++e) { h2[e][0] = b.x; h2[e][1] = b.y; }
        }
        #pragma unroll
        for (int i = 0; i < 18; ++i) {
            ulonglong2 w = *reinterpret_cast<const ulonglong2*>(
                &sw[OFF_NW1 + (ch * 18 + i) * 4]);
            #pragma unroll
            for (int e = 0; e < 2; ++e) {
                float xi = (i < 3) ? in9[e][3 + i] : e2f[e][i - 3];
                unsigned long long pa = pack2(xi, xi);
                ffma2(h2[e][0], pa, w.x);
                ffma2(h2[e][1], pa, w.y);
            }
        }
        #pragma unroll
        for (int e = 0; e < 2; ++e) {
            float a, b;
            unpack2(h2[e][0], a, b); h2[e][0] = pack2(fmaxf(a, 0.f), fmaxf(b, 0.f));
            unpack2(h2[e][1], a, b); h2[e][1] = pack2(fmaxf(a, 0.f), fmaxf(b, 0.f));
        }
        #pragma unroll
        for (int jl = 0; jl < 4; ++jl) {
            int j = ch * 4 + jl;
            const ulonglong2* wp = reinterpret_cast<const ulonglong2*>(
                &sw[OFF_NW2KP + j * 16]);
            ulonglong2 w01 = wp[0], w23 = wp[1], w45 = wp[2], w67 = wp[3];
            #pragma unroll
            for (int e = 0; e < 2; ++e) {
                float a, b;
                unpack2(h2[e][jl >> 1], a, b);
                float hj = (jl & 1) ? b : a;
                unsigned long long pj = pack2(hj, hj);
                ffma2(op[e][0], pj, w01.x);
                ffma2(op[e][1], pj, w01.y);
                ffma2(op[e][2], pj, w23.x);
                ffma2(op[e][3], pj, w23.y);
                ffma2(op[e][4], pj, w45.x);
                ffma2(op[e][5], pj, w45.y);
                ffma2(op[e][6], pj, w67.x);
                ffma2(op[e][7], pj, w67.y);
            }
        }
    }

    // ---- fold + scatter (slot 15 carries the count 1.0) ----
    #pragma unroll
    for (int e = 0; e < 2; ++e) {
        if (!full && e == 1) break;
        float o[16];
        #pragma unroll
        for (int kp = 0; kp < 8; ++kp)
            unpack2(op[e][kp], o[2 * kp], o[2 * kp + 1]);
        o[15] = 1.0f;
        float* dst = &g_x2sum[(size_t)r[e] * 16];
        red4(dst + 0,  o[0],  o[1],  o[2],  o[3]);
        red4(dst + 4,  o[4],  o[5],  o[6],  o[7]);
        red4(dst + 8,  o[8],  o[9],  o[10], o[11]);
        red4(dst + 12, o[12], o[13], o[14], o[15]);
    }
}

// ---------------- graph kernel: per-graph reduce + global MLP + head -------
#define SG_GW1 0
#define SG_GB1 (SG_GW1 + 16 * D2)
#define SG_GW2 (SG_GB1 + D2)
#define SG_GB2 (SG_GW2 + D2 * D3)
#define SG_F1W (SG_GB2 + D3)
#define SG_F1B (SG_F1W + D3 * D5)
#define SG_BNG (SG_F1B + D5)
#define SG_BNB (SG_BNG + D5)
#define SG_F2W (SG_BNB + D5)
#define SG_F2B (SG_F2W + D5 * NC)
#define SG_TOTAL (SG_F2B + NC)

__device__ __forceinline__ int lbound(const int* a, int n, int key) {
    int lo = 0, hi = n;
    while (lo < hi) { int m = (lo + hi) >> 1; if (a[m] < key) lo = m + 1; else hi = m; }
    return lo;
}

__global__ void __launch_bounds__(256)
graph_kernel(
    const int* __restrict__ batch,
    const float* __restrict__ u,
    const float* __restrict__ gw1, const float* __restrict__ gb1,
    const float* __restrict__ gw2, const float* __restrict__ gb2,
    const float* __restrict__ fc1w, const float* __restrict__ fc1b,
    const float* __restrict__ bng, const float* __restrict__ bnb,
    const float* __restrict__ fc2w, const float* __restrict__ fc2b,
    float* __restrict__ out, int N)
{
    __shared__ float swt[SG_TOTAL];
    __shared__ float sred[8][30];
    __shared__ int sse[2];

    int tid = threadIdx.x;
    for (int t = tid; t < 16 * D2; t += blockDim.x) swt[SG_GW1 + t] = gw1[t];
    for (int t = tid; t < D2; t += blockDim.x) swt[SG_GB1 + t] = gb1[t];
    for (int t = tid; t < D2 * D3; t += blockDim.x) swt[SG_GW2 + t] = gw2[t];
    for (int t = tid; t < D3; t += blockDim.x) swt[SG_GB2 + t] = gb2[t];
    for (int t = tid; t < D3 * D5; t += blockDim.x) swt[SG_F1W + t] = fc1w[t];
    for (int t = tid; t < D5; t += blockDim.x) {
        swt[SG_F1B + t] = fc1b[t];
        swt[SG_BNG + t] = bng[t];
        swt[SG_BNB + t] = bnb[t];
    }
    for (int t = tid; t < D5 * NC; t += blockDim.x) swt[SG_F2W + t] = fc2w[t];
    for (int t = tid; t < NC; t += blockDim.x) swt[SG_F2B + t] = fc2b[t];

    int b = blockIdx.x;
    if (tid == 0) {
        sse[0] = lbound(batch, N, b);
        sse[1] = lbound(batch, N, b + 1);
    }
    __syncthreads();
    int s = sse[0], epos = sse[1];
    int nnodes = epos - s;

    float acc[30];
    #pragma unroll
    for (int k = 0; k < 30; ++k) acc[k] = 0.0f;

    for (int n = s + tid; n < epos; n += blockDim.x) {
        const float4* p = reinterpret_cast<const float4*>(&g_x2sum[(size_t)n * 16]);
        float4 a0 = p[0], a1 = p[1], a2 = p[2], a3 = p[3];
        float vv[15] = { a0.x, a0.y, a0.z, a0.w, a1.x, a1.y, a1.z, a1.w,
                         a2.x, a2.y, a2.z, a2.w, a3.x, a3.y, a3.z };
        float cnt = a3.w;
        float inv = 1.0f / fmaxf(cnt, 1.0f);
        #pragma unroll
        for (int k = 0; k < 15; ++k) {
            float t = vv[k] * inv;
            acc[k] += t;
            acc[15 + k] += fmaxf(t, 0.0f);
        }
    }

    #pragma unroll
    for (int k = 0; k < 30; ++k) {
        float v = acc[k];
        #pragma unroll
        for (int off = 16; off > 0; off >>= 1)
            v += __shfl_down_sync(0xFFFFFFFF, v, off);
        acc[k] = v;
    }
    int wid = tid >> 5, lid = tid & 31;
    if (lid == 0) {
        #pragma unroll
        for (int k = 0; k < 30; ++k) sred[wid][k] = acc[k];
    }
    __syncthreads();

    if (tid == 0) {
        float gsum[15], zsum[15];
        #pragma unroll
        for (int k = 0; k < 15; ++k) { gsum[k] = 0.0f; zsum[k] = 0.0f; }
        for (int w = 0; w < (int)(blockDim.x >> 5); ++w) {
            #pragma unroll
            for (int k = 0; k < 15; ++k) {
                gsum[k] += sred[w][k];
                zsum[k] += sred[w][15 + k];
            }
        }

        float cntf = (float)nnodes;
        float invc = 1.0f / fmaxf(cntf, 1.0f);

        float in16[16];
        in16[0] = u[b];
        #pragma unroll
        for (int k = 0; k < 15; ++k) in16[1 + k] = gsum[k] * invc;

        float hg[D2];
        #pragma unroll
        for (int j = 0; j < D2; ++j) hg[j] = swt[SG_GB1 + j];
        #pragma unroll
        for (int i = 0; i < 16; ++i) {
            float xi = in16[i];
            #pragma unroll
            for (int j = 0; j < D2; ++j) hg[j] += xi * swt[SG_GW1 + i * D2 + j];
        }
        #pragma unroll
        for (int j = 0; j < D2; ++j) hg[j] = fmaxf(hg[j], 0.0f);

        float u2[D3];
        #pragma unroll
        for (int k = 0; k < D3; ++k) u2[k] = swt[SG_GB2 + k];
        #pragma unroll
        for (int j = 0; j < D2; ++j) {
            float hj = hg[j];
            #pragma unroll
            for (int k = 0; k < D3; ++k) u2[k] += hj * swt[SG_GW2 + j * D3 + k];
        }

        float invg = 1.0f / (cntf + 1.0f);
        float g[D3];
        #pragma unroll
        for (int k = 0; k < D3; ++k)
            g[k] = (zsum[k] + fmaxf(u2[k], 0.0f)) * invg;

        float h1[D5];
        #pragma unroll
        for (int m = 0; m < D5; ++m) h1[m] = swt[SG_F1B + m];
        #pragma unroll
        for (int k = 0; k < D3; ++k) {
            float gk = g[k];
            #pragma unroll
            for (int m = 0; m < D5; ++m) h1[m] += gk * swt[SG_F1W + k * D5 + m];
        }

        float rs = rsqrtf(1.0f + 1e-5f);
        #pragma unroll
        for (int m = 0; m < D5; ++m)
            h1[m] = fmaxf(h1[m] * (swt[SG_BNG + m] * rs) + swt[SG_BNB + m], 0.0f);

        float lg[NC];
        #pragma unroll
        for (int q = 0; q < NC; ++q) lg[q] = swt[SG_F2B + q];
        #pragma unroll
        for (int m = 0; m < D5; ++m) {
            float hm = h1[m];
            #pragma unroll
            for (int q = 0; q < NC; ++q) lg[q] += hm * swt[SG_F2W + m * NC + q];
        }

        float mx = lg[0];
        #pragma unroll
        for (int q = 1; q < NC; ++q) mx = fmaxf(mx, lg[q]);
        float ssum = 0.0f;
        #pragma unroll
        for (int q = 0; q < NC; ++q) ssum += expf(lg[q] - mx);
        float lse = mx + logf(ssum);
        #pragma unroll
        for (int q = 0; q < NC; ++q) out[b * NC + q] = lg[q] - lse;
    }
}

// ---------------- launch ----------------
extern "C" void kernel_launch(void* const* d_in, const int* in_sizes, int n_in,
                              void* d_out, int out_size) {
    const float* x     = (const float*)d_in[0];
    const int*   ei    = (const int*)d_in[1];
    const float* ea    = (const float*)d_in[2];
    const float* u     = (const float*)d_in[3];
    const int*   batch = (const int*)d_in[4];
    const float* ew1   = (const float*)d_in[5];
    const float* eb1   = (const float*)d_in[6];
    const float* ew2   = (const float*)d_in[7];
    const float* eb2   = (const float*)d_in[8];
    const float* nw1   = (const float*)d_in[9];
    const float* nb1   = (const float*)d_in[10];
    const float* nw2   = (const float*)d_in[11];
    const float* nb2   = (const float*)d_in[12];
    const float* gw1   = (const float*)d_in[13];
    const float* gb1   = (const float*)d_in[14];
    const float* gw2   = (const float*)d_in[15];
    const float* gb2   = (const float*)d_in[16];
    const float* fc1w  = (const float*)d_in[17];
    const float* fc1b  = (const float*)d_in[18];
    const float* bng   = (const float*)d_in[19];
    const float* bnb   = (const float*)d_in[20];
    const float* fc2w  = (const float*)d_in[21];
    const float* fc2b  = (const float*)d_in[22];
    float* out = (float*)d_out;

    int N = in_sizes[0] / 3;   // nodes
    int E = in_sizes[1] / 2;   // edges
    int B = in_sizes[3];       // graphs

    const int* row = ei;
    const int* col = ei + E;

    zero_kernel<<<512, 256>>>(N);

    int P = (E + 1) / 2;       // 2 edges per thread
    edge_kernel<<<(P + 127) / 128, 128>>>(x, row, col, ea,
                                          ew1, eb1, ew2, eb2,
                                          nw1, nb1, nw2, nb2, P, E);

    graph_kernel<<<B, 256>>>(batch, u,
                             gw1, gb1, gw2, gb2,
                             fc1w, fc1b, bng, bnb, fc2w, fc2b, out, N);
}

// round 12
// speedup vs baseline: 1.0221x; 1.0030x over previous
#include <cuda_runtime.h>
#include <math.h>

// Problem dims (fixed by setup_inputs)
#define MAXN 100000
#define MAXB 256
#define D2 50
#define D3 15
#define D5 10
#define NC 6

// ---------------- device scratch ----------------
// per-node record: 15 accum floats + count in slot 15 (16 floats = 64B)
// Zero-initialized at module load; graph_kernel restores zeros after reading,
// so no separate zeroing kernel is needed (invariant across graph replays).
__device__ __align__(16) float g_x2sum[MAXN * 16];

// ---------------- packed f32x2 helpers ----------------
__device__ __forceinline__ unsigned long long pack2(float a, float b) {
    unsigned long long r;
    asm("mov.b64 %0, {%1, %2};" : "=l"(r) : "f"(a), "f"(b));
    return r;
}
__device__ __forceinline__ void unpack2(unsigned long long v, float& a, float& b) {
    asm("mov.b64 {%0, %1}, %2;" : "=f"(a), "=f"(b) : "l"(v));
}
__device__ __forceinline__ void ffma2(unsigned long long& acc,
                                      unsigned long long a, unsigned long long b) {
    asm("fma.rn.f32x2 %0, %1, %2, %0;" : "+l"(acc) : "l"(a), "l"(b));
}
__device__ __forceinline__ void red4(float* p, float a, float b, float c, float d) {
    asm volatile("red.global.add.v4.f32 [%0], {%1, %2, %3, %4};"
                 :: "l"(p), "f"(a), "f"(b), "f"(c), "f"(d) : "memory");
}

// ---------------- SMEM weight layout (floats) -----------------------------
// Layer-1 weights chunk-major:  [13 chunks][in][4 j]   (j = ch*4 + jl, pad 52)
// Layer-1 bias:                 [52] linear (j index)
// Layer-2 weights k-pair-major: [52 j][16 k]  (float t = j*16 + k, pad)
// Layer-2 bias:                 [16] linear (k index)
#define OFF_EW1   0                      // 13*9*4  = 468
#define OFF_EB1   468                    // 52
#define OFF_EW2KP 520                    // 52*16   = 832
#define OFF_EB2   1352                   // 16
#define OFF_NW1   1368                   // 13*18*4 = 936
#define OFF_NB1   2304                   // 52
#define OFF_NW2KP 2356                   // 832
#define OFF_NB2   3188                   // 16
#define SW_TOTAL  3204

// ---------------- edge kernel: 4 edges/thread, fused chunk consumption ----
__global__ void __launch_bounds__(128)
edge_kernel(
    const float* __restrict__ x,
    const int* __restrict__ row,
    const int* __restrict__ col,
    const float* __restrict__ ea,
    const float* __restrict__ ew1, const float* __restrict__ eb1,
    const float* __restrict__ ew2, const float* __restrict__ eb2,
    const float* __restrict__ nw1, const float* __restrict__ nb1,
    const float* __restrict__ nw2, const float* __restrict__ nb2,
    int P, int E)
{
    __shared__ __align__(16) float sw[SW_TOTAL];

    // ---- stage weights (remapped layouts) ----
    for (int t = threadIdx.x; t < 13 * 9 * 4; t += blockDim.x) {
        int ch = t / 36, rem = t % 36, i = rem / 4, jl = rem % 4;
        int j = ch * 4 + jl;
        sw[OFF_EW1 + t] = (j < D2) ? ew1[i * D2 + j] : 0.0f;
    }
    for (int t = threadIdx.x; t < 52; t += blockDim.x)
        sw[OFF_EB1 + t] = (t < D2) ? eb1[t] : 0.0f;
    for (int t = threadIdx.x; t < 52 * 16; t += blockDim.x) {
        int j = t / 16, k = t % 16;
        sw[OFF_EW2KP + t] = (j < D2 && k < D3) ? ew2[j * D3 + k] : 0.0f;
    }
    for (int t = threadIdx.x; t < 16; t += blockDim.x)
        sw[OFF_EB2 + t] = (t < D3) ? eb2[t] : 0.0f;
    for (int t = threadIdx.x; t < 13 * 18 * 4; t += blockDim.x) {
        int ch = t / 72, rem = t % 72, i = rem / 4, jl = rem % 4;
        int j = ch * 4 + jl;
        sw[OFF_NW1 + t] = (j < D2) ? nw1[i * D2 + j] : 0.0f;
    }
    for (int t = threadIdx.x; t < 52; t += blockDim.x)
        sw[OFF_NB1 + t] = (t < D2) ? nb1[t] : 0.0f;
    for (int t = threadIdx.x; t < 52 * 16; t += blockDim.x) {
        int j = t / 16, k = t % 16;
        sw[OFF_NW2KP + t] = (j < D2 && k < D3) ? nw2[j * D3 + k] : 0.0f;
    }
    for (int t = threadIdx.x; t < 16; t += blockDim.x)
        sw[OFF_NB2 + t] = (t < D3) ? nb2[t] : 0.0f;
    __syncthreads();

    int p = blockIdx.x * blockDim.x + threadIdx.x;
    if (p >= P) return;

    int e0 = 4 * p;
    bool full = (e0 + 3 < E);

    // ---- gather indices + inputs for 4 edges ----
    int r[4], c[4];
    float in9[4][9];
    if (full) {
        int4 rr = *reinterpret_cast<const int4*>(row + e0);
        int4 cc = *reinterpret_cast<const int4*>(col + e0);
        r[0] = rr.x; r[1] = rr.y; r[2] = rr.z; r[3] = rr.w;
        c[0] = cc.x; c[1] = cc.y; c[2] = cc.z; c[3] = cc.w;
        const float4* ea4 = reinterpret_cast<const float4*>(ea + 3 * e0);
        float4 a0 = ea4[0], a1 = ea4[1], a2 = ea4[2];
        in9[0][6] = a0.x; in9[0][7] = a0.y; in9[0][8] = a0.z;
        in9[1][6] = a0.w; in9[1][7] = a1.x; in9[1][8] = a1.y;
        in9[2][6] = a1.z; in9[2][7] = a1.w; in9[2][8] = a2.x;
        in9[3][6] = a2.y; in9[3][7] = a2.z; in9[3][8] = a2.w;
    } else {
        #pragma unroll
        for (int e = 0; e < 4; ++e) {
            int idx = min(e0 + e, E - 1);
            r[e] = row[idx]; c[e] = col[idx];
            in9[e][6] = ea[3 * idx + 0];
            in9[e][7] = ea[3 * idx + 1];
            in9[e][8] = ea[3 * idx + 2];
        }
    }
    #pragma unroll
    for (int e = 0; e < 4; ++e) {
        in9[e][0] = x[3 * r[e] + 0];
        in9[e][1] = x[3 * r[e] + 1];
        in9[e][2] = x[3 * r[e] + 2];
        in9[e][3] = x[3 * c[e] + 0];
        in9[e][4] = x[3 * c[e] + 1];
        in9[e][5] = x[3 * c[e] + 2];
    }

    // ================= EDGE MLP (fused layers) =================
    unsigned long long e2p[4][8];
    {
        const ulonglong2* bv = reinterpret_cast<const ulonglong2*>(&sw[OFF_EB2]);
        #pragma unroll
        for (int q = 0; q < 4; ++q) {
            ulonglong2 b = bv[q];
            #pragma unroll
            for (int e = 0; e < 4; ++e) {
                e2p[e][2 * q + 0] = b.x;
                e2p[e][2 * q + 1] = b.y;
            }
        }
    }
    #pragma unroll
    for (int ch = 0; ch < 13; ++ch) {
        unsigned long long h[4][2];
        {
            ulonglong2 b = *reinterpret_cast<const ulonglong2*>(&sw[OFF_EB1 + 4 * ch]);
            #pragma unroll
            for (int e = 0; e < 4; ++e) { h[e][0] = b.x; h[e][1] = b.y; }
        }
        #pragma unroll
        for (int i = 0; i < 9; ++i) {
            ulonglong2 w = *reinterpret_cast<const ulonglong2*>(
                &sw[OFF_EW1 + (ch * 9 + i) * 4]);
            #pragma unroll
            for (int e = 0; e < 4; ++e) {
                unsigned long long pa = pack2(in9[e][i], in9[e][i]);
                ffma2(h[e][0], pa, w.x);
                ffma2(h[e][1], pa, w.y);
            }
        }
        #pragma unroll
        for (int e = 0; e < 4; ++e) {
            float a, b;
            unpack2(h[e][0], a, b); h[e][0] = pack2(fmaxf(a, 0.f), fmaxf(b, 0.f));
            unpack2(h[e][1], a, b); h[e][1] = pack2(fmaxf(a, 0.f), fmaxf(b, 0.f));
        }
        #pragma unroll
        for (int jl = 0; jl < 4; ++jl) {
            int j = ch * 4 + jl;
            const ulonglong2* wp = reinterpret_cast<const ulonglong2*>(
                &sw[OFF_EW2KP + j * 16]);
            ulonglong2 w01 = wp[0], w23 = wp[1], w45 = wp[2], w67 = wp[3];
            #pragma unroll
            for (int e = 0; e < 4; ++e) {
                float a, b;
                unpack2(h[e][jl >> 1], a, b);
                float hj = (jl & 1) ? b : a;
                unsigned long long pj = pack2(hj, hj);
                ffma2(e2p[e][0], pj, w01.x);
                ffma2(e2p[e][1], pj, w01.y);
                ffma2(e2p[e][2], pj, w23.x);
                ffma2(e2p[e][3], pj, w23.y);
                ffma2(e2p[e][4], pj, w45.x);
                ffma2(e2p[e][5], pj, w45.y);
                ffma2(e2p[e][6], pj, w67.x);
                ffma2(e2p[e][7], pj, w67.y);
            }
        }
    }
    // fold e2 partials to scalars (bias already in)
    float e2f[4][15];
    #pragma unroll
    for (int e = 0; e < 4; ++e) {
        #pragma unroll
        for (int kp = 0; kp < 8; ++kp) {
            float lo, hi;
            unpack2(e2p[e][kp], lo, hi);
            if (2 * kp < 15)     e2f[e][2 * kp] = lo;
            if (2 * kp + 1 < 15) e2f[e][2 * kp + 1] = hi;
        }
    }

    // ================= NODE MLP (fused layers) =================
    unsigned long long op[4][8];
    {
        const ulonglong2* bv = reinterpret_cast<const ulonglong2*>(&sw[OFF_NB2]);
        #pragma unroll
        for (int q = 0; q < 4; ++q) {
            ulonglong2 b = bv[q];
            #pragma unroll
            for (int e = 0; e < 4; ++e) {
                op[e][2 * q + 0] = b.x;
                op[e][2 * q + 1] = b.y;
            }
        }
    }
    #pragma unroll
    for (int ch = 0; ch < 13; ++ch) {
        unsigned long long h2[4][2];
        {
            ulonglong2 b = *reinterpret_cast<const ulonglong2*>(&sw[OFF_NB1 + 4 * ch]);
            #pragma unroll
            for (int e = 0; e < 4; ++e) { h2[e][0] = b.x; h2[e][1] = b.y; }
        }
        #pragma unroll
        for (int i = 0; i < 18; ++i) {
            ulonglong2 w = *reinterpret_cast<const ulonglong2*>(
                &sw[OFF_NW1 + (ch * 18 + i) * 4]);
            #pragma unroll
            for (int e = 0; e < 4; ++e) {
                float xi = (i < 3) ? in9[e][3 + i] : e2f[e][i - 3];
                unsigned long long pa = pack2(xi, xi);
                ffma2(h2[e][0], pa, w.x);
                ffma2(h2[e][1], pa, w.y);
            }
        }
        #pragma unroll
        for (int e = 0; e < 4; ++e) {
            float a, b;
            unpack2(h2[e][0], a, b); h2[e][0] = pack2(fmaxf(a, 0.f), fmaxf(b, 0.f));
            unpack2(h2[e][1], a, b); h2[e][1] = pack2(fmaxf(a, 0.f), fmaxf(b, 0.f));
        }
        #pragma unroll
        for (int jl = 0; jl < 4; ++jl) {
            int j = ch * 4 + jl;
            const ulonglong2* wp = reinterpret_cast<const ulonglong2*>(
                &sw[OFF_NW2KP + j * 16]);
            ulonglong2 w01 = wp[0], w23 = wp[1], w45 = wp[2], w67 = wp[3];
            #pragma unroll
            for (int e = 0; e < 4; ++e) {
                float a, b;
                unpack2(h2[e][jl >> 1], a, b);
                float hj = (jl & 1) ? b : a;
                unsigned long long pj = pack2(hj, hj);
                ffma2(op[e][0], pj, w01.x);
                ffma2(op[e][1], pj, w01.y);
                ffma2(op[e][2], pj, w23.x);
                ffma2(op[e][3], pj, w23.y);
                ffma2(op[e][4], pj, w45.x);
                ffma2(op[e][5], pj, w45.y);
                ffma2(op[e][6], pj, w67.x);
                ffma2(op[e][7], pj, w67.y);
            }
        }
    }

    // ---- fold + scatter (slot 15 carries the count 1.0) ----
    #pragma unroll
    for (int e = 0; e < 4; ++e) {
        if (!full && (e0 + e >= E)) break;
        float o[16];
        #pragma unroll
        for (int kp = 0; kp < 8; ++kp)
            unpack2(op[e][kp], o[2 * kp], o[2 * kp + 1]);
        o[15] = 1.0f;
        float* dst = &g_x2sum[(size_t)r[e] * 16];
        red4(dst + 0,  o[0],  o[1],  o[2],  o[3]);
        red4(dst + 4,  o[4],  o[5],  o[6],  o[7]);
        red4(dst + 8,  o[8],  o[9],  o[10], o[11]);
        red4(dst + 12, o[12], o[13], o[14], o[15]);
    }
}

// ---------------- graph kernel: per-graph reduce + global MLP + head -------
// Also RE-ZEROES every node record it reads, restoring the accumulator
// invariant for the next graph replay (replaces the zero_kernel launch).
#define SG_GW1 0
#define SG_GB1 (SG_GW1 + 16 * D2)
#define SG_GW2 (SG_GB1 + D2)
#define SG_GB2 (SG_GW2 + D2 * D3)
#define SG_F1W (SG_GB2 + D3)
#define SG_F1B (SG_F1W + D3 * D5)
#define SG_BNG (SG_F1B + D5)
#define SG_BNB (SG_BNG + D5)
#define SG_F2W (SG_BNB + D5)
#define SG_F2B (SG_F2W + D5 * NC)
#define SG_TOTAL (SG_F2B + NC)

__device__ __forceinline__ int lbound(const int* a, int n, int key) {
    int lo = 0, hi = n;
    while (lo < hi) { int m = (lo + hi) >> 1; if (a[m] < key) lo = m + 1; else hi = m; }
    return lo;
}

__global__ void __launch_bounds__(256)
graph_kernel(
    const int* __restrict__ batch,
    const float* __restrict__ u,
    const float* __restrict__ gw1, const float* __restrict__ gb1,
    const float* __restrict__ gw2, const float* __restrict__ gb2,
    const float* __restrict__ fc1w, const float* __restrict__ fc1b,
    const float* __restrict__ bng, const float* __restrict__ bnb,
    const float* __restrict__ fc2w, const float* __restrict__ fc2b,
    float* __restrict__ out, int N)
{
    __shared__ float swt[SG_TOTAL];
    __shared__ float sred[8][30];
    __shared__ int sse[2];

    int tid = threadIdx.x;
    for (int t = tid; t < 16 * D2; t += blockDim.x) swt[SG_GW1 + t] = gw1[t];
    for (int t = tid; t < D2; t += blockDim.x) swt[SG_GB1 + t] = gb1[t];
    for (int t = tid; t < D2 * D3; t += blockDim.x) swt[SG_GW2 + t] = gw2[t];
    for (int t = tid; t < D3; t += blockDim.x) swt[SG_GB2 + t] = gb2[t];
    for (int t = tid; t < D3 * D5; t += blockDim.x) swt[SG_F1W + t] = fc1w[t];
    for (int t = tid; t < D5; t += blockDim.x) {
        swt[SG_F1B + t] = fc1b[t];
        swt[SG_BNG + t] = bng[t];
        swt[SG_BNB + t] = bnb[t];
    }
    for (int t = tid; t < D5 * NC; t += blockDim.x) swt[SG_F2W + t] = fc2w[t];
    for (int t = tid; t < NC; t += blockDim.x) swt[SG_F2B + t] = fc2b[t];

    int b = blockIdx.x;
    if (tid == 0) {
        sse[0] = lbound(batch, N, b);
        sse[1] = lbound(batch, N, b + 1);
    }
    __syncthreads();
    int s = sse[0], epos = sse[1];
    int nnodes = epos - s;

    float acc[30];
    #pragma unroll
    for (int k = 0; k < 30; ++k) acc[k] = 0.0f;

    const float4 z4 = make_float4(0.f, 0.f, 0.f, 0.f);
    for (int n = s + tid; n < epos; n += blockDim.x) {
        float4* p = reinterpret_cast<float4*>(&g_x2sum[(size_t)n * 16]);
        float4 a0 = p[0], a1 = p[1], a2 = p[2], a3 = p[3];
        // restore zeros for the next replay (replaces zero_kernel)
        p[0] = z4; p[1] = z4; p[2] = z4; p[3] = z4;
        float vv[15] = { a0.x, a0.y, a0.z, a0.w, a1.x, a1.y, a1.z, a1.w,
                         a2.x, a2.y, a2.z, a2.w, a3.x, a3.y, a3.z };
        float cnt = a3.w;
        float inv = 1.0f / fmaxf(cnt, 1.0f);
        #pragma unroll
        for (int k = 0; k < 15; ++k) {
            float t = vv[k] * inv;
            acc[k] += t;
            acc[15 + k] += fmaxf(t, 0.0f);
        }
    }

    #pragma unroll
    for (int k = 0; k < 30; ++k) {
        float v = acc[k];
        #pragma unroll
        for (int off = 16; off > 0; off >>= 1)
            v += __shfl_down_sync(0xFFFFFFFF, v, off);
        acc[k] = v;
    }
    int wid = tid >> 5, lid = tid & 31;
    if (lid == 0) {
        #pragma unroll
        for (int k = 0; k < 30; ++k) sred[wid][k] = acc[k];
    }
    __syncthreads();

    if (tid == 0) {
        float gsum[15], zsum[15];
        #pragma unroll
        for (int k = 0; k < 15; ++k) { gsum[k] = 0.0f; zsum[k] = 0.0f; }
        for (int w = 0; w < (int)(blockDim.x >> 5); ++w) {
            #pragma unroll
            for (int k = 0; k < 15; ++k) {
                gsum[k] += sred[w][k];
                zsum[k] += sred[w][15 + k];
            }
        }

        float cntf = (float)nnodes;
        float invc = 1.0f / fmaxf(cntf, 1.0f);

        float in16[16];
        in16[0] = u[b];
        #pragma unroll
        for (int k = 0; k < 15; ++k) in16[1 + k] = gsum[k] * invc;

        float hg[D2];
        #pragma unroll
        for (int j = 0; j < D2; ++j) hg[j] = swt[SG_GB1 + j];
        #pragma unroll
        for (int i = 0; i < 16; ++i) {
            float xi = in16[i];
            #pragma unroll
            for (int j = 0; j < D2; ++j) hg[j] += xi * swt[SG_GW1 + i * D2 + j];
        }
        #pragma unroll
        for (int j = 0; j < D2; ++j) hg[j] = fmaxf(hg[j], 0.0f);

        float u2[D3];
        #pragma unroll
        for (int k = 0; k < D3; ++k) u2[k] = swt[SG_GB2 + k];
        #pragma unroll
        for (int j = 0; j < D2; ++j) {
            float hj = hg[j];
            #pragma unroll
            for (int k = 0; k < D3; ++k) u2[k] += hj * swt[SG_GW2 + j * D3 + k];
        }

        float invg = 1.0f / (cntf + 1.0f);
        float g[D3];
        #pragma unroll
        for (int k = 0; k < D3; ++k)
            g[k] = (zsum[k] + fmaxf(u2[k], 0.0f)) * invg;

        float h1[D5];
        #pragma unroll
        for (int m = 0; m < D5; ++m) h1[m] = swt[SG_F1B + m];
        #pragma unroll
        for (int k = 0; k < D3; ++k) {
            float gk = g[k];
            #pragma unroll
            for (int m = 0; m < D5; ++m) h1[m] += gk * swt[SG_F1W + k * D5 + m];
        }

        float rs = rsqrtf(1.0f + 1e-5f);
        #pragma unroll
        for (int m = 0; m < D5; ++m)
            h1[m] = fmaxf(h1[m] * (swt[SG_BNG + m] * rs) + swt[SG_BNB + m], 0.0f);

        float lg[NC];
        #pragma unroll
        for (int q = 0; q < NC; ++q) lg[q] = swt[SG_F2B + q];
        #pragma unroll
        for (int m = 0; m < D5; ++m) {
            float hm = h1[m];
            #pragma unroll
            for (int q = 0; q < NC; ++q) lg[q] += hm * swt[SG_F2W + m * NC + q];
        }

        float mx = lg[0];
        #pragma unroll
        for (int q = 1; q < NC; ++q) mx = fmaxf(mx, lg[q]);
        float ssum = 0.0f;
        #pragma unroll
        for (int q = 0; q < NC; ++q) ssum += expf(lg[q] - mx);
        float lse = mx + logf(ssum);
        #pragma unroll
        for (int q = 0; q < NC; ++q) out[b * NC + q] = lg[q] - lse;
    }
}

// ---------------- launch ----------------
extern "C" void kernel_launch(void* const* d_in, const int* in_sizes, int n_in,
                              void* d_out, int out_size) {
    const float* x     = (const float*)d_in[0];
    const int*   ei    = (const int*)d_in[1];
    const float* ea    = (const float*)d_in[2];
    const float* u     = (const float*)d_in[3];
    const int*   batch = (const int*)d_in[4];
    const float* ew1   = (const float*)d_in[5];
    const float* eb1   = (const float*)d_in[6];
    const float* ew2   = (const float*)d_in[7];
    const float* eb2   = (const float*)d_in[8];
    const float* nw1   = (const float*)d_in[9];
    const float* nb1   = (const float*)d_in[10];
    const float* nw2   = (const float*)d_in[11];
    const float* nb2   = (const float*)d_in[12];
    const float* gw1   = (const float*)d_in[13];
    const float* gb1   = (const float*)d_in[14];
    const float* gw2   = (const float*)d_in[15];
    const float* gb2   = (const float*)d_in[16];
    const float* fc1w  = (const float*)d_in[17];
    const float* fc1b  = (const float*)d_in[18];
    const float* bng   = (const float*)d_in[19];
    const float* bnb   = (const float*)d_in[20];
    const float* fc2w  = (const float*)d_in[21];
    const float* fc2b  = (const float*)d_in[22];
    float* out = (float*)d_out;

    int N = in_sizes[0] / 3;   // nodes
    int E = in_sizes[1] / 2;   // edges
    int B = in_sizes[3];       // graphs

    const int* row = ei;
    const int* col = ei + E;

    int P = (E + 3) / 4;       // 4 edges per thread
    edge_kernel<<<(P + 127) / 128, 128>>>(x, row, col, ea,
                                          ew1, eb1, ew2, eb2,
                                          nw1, nb1, nw2, nb2, P, E);

    graph_kernel<<<B, 256>>>(batch, u,
                             gw1, gb1, gw2, gb2,
                             fc1w, fc1b, bng, bnb, fc2w, fc2b, out, N);
}

// round 13
// speedup vs baseline: 1.0510x; 1.0283x over previous
#include <cuda_runtime.h>
#include <math.h>

// Problem dims (fixed by setup_inputs)
#define MAXN 100000
#define MAXB 256
#define D2 50
#define D3 15
#define D5 10
#define NC 6

// ---------------- device scratch ----------------
// per-node record: 15 accum floats + count in slot 15 (16 floats = 64B)
// Zero-initialized at module load; zero_kernel (launched AFTER graph_kernel)
// restores the invariant for the next graph replay.
__device__ __align__(16) float g_x2sum[MAXN * 16];

// ---------------- packed f32x2 helpers ----------------
__device__ __forceinline__ unsigned long long pack2(float a, float b) {
    unsigned long long r;
    asm("mov.b64 %0, {%1, %2};" : "=l"(r) : "f"(a), "f"(b));
    return r;
}
__device__ __forceinline__ void unpack2(unsigned long long v, float& a, float& b) {
    asm("mov.b64 {%0, %1}, %2;" : "=f"(a), "=f"(b) : "l"(v));
}
__device__ __forceinline__ void ffma2(unsigned long long& acc,
                                      unsigned long long a, unsigned long long b) {
    asm("fma.rn.f32x2 %0, %1, %2, %0;" : "+l"(acc) : "l"(a), "l"(b));
}
__device__ __forceinline__ void red4(float* p, float a, float b, float c, float d) {
    asm volatile("red.global.add.v4.f32 [%0], {%1, %2, %3, %4};"
                 :: "l"(p), "f"(a), "f"(b), "f"(c), "f"(d) : "memory");
}

// ---------------- zero accumulators (runs after graph_kernel) -------------
__global__ void zero_kernel(int N) {
    int tid = blockIdx.x * blockDim.x + threadIdx.x;
    int stride = gridDim.x * blockDim.x;
    int total = N * 4;  // float4 units
    float4 z = make_float4(0.f, 0.f, 0.f, 0.f);
    float4* p = reinterpret_cast<float4*>(g_x2sum);
    for (int t = tid; t < total; t += stride) p[t] = z;
}

// ---------------- SMEM weight layout (floats) -----------------------------
#define OFF_EW1   0                      // 13*9*4  = 468
#define OFF_EB1   468                    // 52
#define OFF_EW2KP 520                    // 52*16   = 832
#define OFF_EB2   1352                   // 16
#define OFF_NW1   1368                   // 13*18*4 = 936
#define OFF_NB1   2304                   // 52
#define OFF_NW2KP 2356                   // 832
#define OFF_NB2   3188                   // 16
#define SW_TOTAL  3204

// ---------------- edge kernel: 4 edges/thread, fused chunk consumption ----
__global__ void __launch_bounds__(128)
edge_kernel(
    const float* __restrict__ x,
    const int* __restrict__ row,
    const int* __restrict__ col,
    const float* __restrict__ ea,
    const float* __restrict__ ew1, const float* __restrict__ eb1,
    const float* __restrict__ ew2, const float* __restrict__ eb2,
    const float* __restrict__ nw1, const float* __restrict__ nb1,
    const float* __restrict__ nw2, const float* __restrict__ nb2,
    int P, int E)
{
    __shared__ __align__(16) float sw[SW_TOTAL];

    // ---- stage weights (remapped layouts) ----
    for (int t = threadIdx.x; t < 13 * 9 * 4; t += blockDim.x) {
        int ch = t / 36, rem = t % 36, i = rem / 4, jl = rem % 4;
        int j = ch * 4 + jl;
        sw[OFF_EW1 + t] = (j < D2) ? ew1[i * D2 + j] : 0.0f;
    }
    for (int t = threadIdx.x; t < 52; t += blockDim.x)
        sw[OFF_EB1 + t] = (t < D2) ? eb1[t] : 0.0f;
    for (int t = threadIdx.x; t < 52 * 16; t += blockDim.x) {
        int j = t / 16, k = t % 16;
        sw[OFF_EW2KP + t] = (j < D2 && k < D3) ? ew2[j * D3 + k] : 0.0f;
    }
    for (int t = threadIdx.x; t < 16; t += blockDim.x)
        sw[OFF_EB2 + t] = (t < D3) ? eb2[t] : 0.0f;
    for (int t = threadIdx.x; t < 13 * 18 * 4; t += blockDim.x) {
        int ch = t / 72, rem = t % 72, i = rem / 4, jl = rem % 4;
        int j = ch * 4 + jl;
        sw[OFF_NW1 + t] = (j < D2) ? nw1[i * D2 + j] : 0.0f;
    }
    for (int t = threadIdx.x; t < 52; t += blockDim.x)
        sw[OFF_NB1 + t] = (t < D2) ? nb1[t] : 0.0f;
    for (int t = threadIdx.x; t < 52 * 16; t += blockDim.x) {
        int j = t / 16, k = t % 16;
        sw[OFF_NW2KP + t] = (j < D2 && k < D3) ? nw2[j * D3 + k] : 0.0f;
    }
    for (int t = threadIdx.x; t < 16; t += blockDim.x)
        sw[OFF_NB2 + t] = (t < D3) ? nb2[t] : 0.0f;
    __syncthreads();

    int p = blockIdx.x * blockDim.x + threadIdx.x;
    if (p >= P) return;

    int e0 = 4 * p;
    bool full = (e0 + 3 < E);

    // ---- gather indices + inputs for 4 edges ----
    int r[4], c[4];
    float in9[4][9];
    if (full) {
        int4 rr = *reinterpret_cast<const int4*>(row + e0);
        int4 cc = *reinterpret_cast<const int4*>(col + e0);
        r[0] = rr.x; r[1] = rr.y; r[2] = rr.z; r[3] = rr.w;
        c[0] = cc.x; c[1] = cc.y; c[2] = cc.z; c[3] = cc.w;
        const float4* ea4 = reinterpret_cast<const float4*>(ea + 3 * e0);
        float4 a0 = ea4[0], a1 = ea4[1], a2 = ea4[2];
        in9[0][6] = a0.x; in9[0][7] = a0.y; in9[0][8] = a0.z;
        in9[1][6] = a0.w; in9[1][7] = a1.x; in9[1][8] = a1.y;
        in9[2][6] = a1.z; in9[2][7] = a1.w; in9[2][8] = a2.x;
        in9[3][6] = a2.y; in9[3][7] = a2.z; in9[3][8] = a2.w;
    } else {
        #pragma unroll
        for (int e = 0; e < 4; ++e) {
            int idx = min(e0 + e, E - 1);
            r[e] = row[idx]; c[e] = col[idx];
            in9[e][6] = ea[3 * idx + 0];
            in9[e][7] = ea[3 * idx + 1];
            in9[e][8] = ea[3 * idx + 2];
        }
    }
    #pragma unroll
    for (int e = 0; e < 4; ++e) {
        in9[e][0] = x[3 * r[e] + 0];
        in9[e][1] = x[3 * r[e] + 1];
        in9[e][2] = x[3 * r[e] + 2];
        in9[e][3] = x[3 * c[e] + 0];
        in9[e][4] = x[3 * c[e] + 1];
        in9[e][5] = x[3 * c[e] + 2];
    }

    // ================= EDGE MLP (fused layers) =================
    unsigned long long e2p[4][8];
    {
        const ulonglong2* bv = reinterpret_cast<const ulonglong2*>(&sw[OFF_EB2]);
        #pragma unroll
        for (int q = 0; q < 4; ++q) {
            ulonglong2 b = bv[q];
            #pragma unroll
            for (int e = 0; e < 4; ++e) {
                e2p[e][2 * q + 0] = b.x;
                e2p[e][2 * q + 1] = b.y;
            }
        }
    }
    #pragma unroll
    for (int ch = 0; ch < 13; ++ch) {
        unsigned long long h[4][2];
        {
            ulonglong2 b = *reinterpret_cast<const ulonglong2*>(&sw[OFF_EB1 + 4 * ch]);
            #pragma unroll
            for (int e = 0; e < 4; ++e) { h[e][0] = b.x; h[e][1] = b.y; }
        }
        #pragma unroll
        for (int i = 0; i < 9; ++i) {
            ulonglong2 w = *reinterpret_cast<const ulonglong2*>(
                &sw[OFF_EW1 + (ch * 9 + i) * 4]);
            #pragma unroll
            for (int e = 0; e < 4; ++e) {
                unsigned long long pa = pack2(in9[e][i], in9[e][i]);
                ffma2(h[e][0], pa, w.x);
                ffma2(h[e][1], pa, w.y);
            }
        }
        #pragma unroll
        for (int e = 0; e < 4; ++e) {
            float a, b;
            unpack2(h[e][0], a, b); h[e][0] = pack2(fmaxf(a, 0.f), fmaxf(b, 0.f));
            unpack2(h[e][1], a, b); h[e][1] = pack2(fmaxf(a, 0.f), fmaxf(b, 0.f));
        }
        #pragma unroll
        for (int jl = 0; jl < 4; ++jl) {
            int j = ch * 4 + jl;
            const ulonglong2* wp = reinterpret_cast<const ulonglong2*>(
                &sw[OFF_EW2KP + j * 16]);
            ulonglong2 w01 = wp[0], w23 = wp[1], w45 = wp[2], w67 = wp[3];
            #pragma unroll
            for (int e = 0; e < 4; ++e) {
                float a, b;
                unpack2(h[e][jl >> 1], a, b);
                float hj = (jl & 1) ? b : a;
                unsigned long long pj = pack2(hj, hj);
                ffma2(e2p[e][0], pj, w01.x);
                ffma2(e2p[e][1], pj, w01.y);
                ffma2(e2p[e][2], pj, w23.x);
                ffma2(e2p[e][3], pj, w23.y);
                ffma2(e2p[e][4], pj, w45.x);
                ffma2(e2p[e][5], pj, w45.y);
                ffma2(e2p[e][6], pj, w67.x);
                ffma2(e2p[e][7], pj, w67.y);
            }
        }
    }
    // fold e2 partials to scalars (bias already in)
    float e2f[4][15];
    #pragma unroll
    for (int e = 0; e < 4; ++e) {
        #pragma unroll
        for (int kp = 0; kp < 8; ++kp) {
            float lo, hi;
            unpack2(e2p[e][kp], lo, hi);
            if (2 * kp < 15)     e2f[e][2 * kp] = lo;
            if (2 * kp + 1 < 15) e2f[e][2 * kp + 1] = hi;
        }
    }

    // ================= NODE MLP (fused layers) =================
    unsigned long long op[4][8];
    {
        const ulonglong2* bv = reinterpret_cast<const ulonglong2*>(&sw[OFF_NB2]);
        #pragma unroll
        for (int q = 0; q < 4; ++q) {
            ulonglong2 b = bv[q];
            #pragma unroll
            for (int e = 0; e < 4; ++e) {
                op[e][2 * q + 0] = b.x;
                op[e][2 * q + 1] = b.y;
            }
        }
    }
    #pragma unroll
    for (int ch = 0; ch < 13; ++ch) {
        unsigned long long h2[4][2];
        {
            ulonglong2 b = *reinterpret_cast<const ulonglong2*>(&sw[OFF_NB1 + 4 * ch]);
            #pragma unroll
            for (int e = 0; e < 4; ++e) { h2[e][0] = b.x; h2[e][1] = b.y; }
        }
        #pragma unroll
        for (int i = 0; i < 18; ++i) {
            ulonglong2 w = *reinterpret_cast<const ulonglong2*>(
                &sw[OFF_NW1 + (ch * 18 + i) * 4]);
            #pragma unroll
            for (int e = 0; e < 4; ++e) {
                float xi = (i < 3) ? in9[e][3 + i] : e2f[e][i - 3];
                unsigned long long pa = pack2(xi, xi);
                ffma2(h2[e][0], pa, w.x);
                ffma2(h2[e][1], pa, w.y);
            }
        }
        #pragma unroll
        for (int e = 0; e < 4; ++e) {
            float a, b;
            unpack2(h2[e][0], a, b); h2[e][0] = pack2(fmaxf(a, 0.f), fmaxf(b, 0.f));
            unpack2(h2[e][1], a, b); h2[e][1] = pack2(fmaxf(a, 0.f), fmaxf(b, 0.f));
        }
        #pragma unroll
        for (int jl = 0; jl < 4; ++jl) {
            int j = ch * 4 + jl;
            const ulonglong2* wp = reinterpret_cast<const ulonglong2*>(
                &sw[OFF_NW2KP + j * 16]);
            ulonglong2 w01 = wp[0], w23 = wp[1], w45 = wp[2], w67 = wp[3];
            #pragma unroll
            for (int e = 0; e < 4; ++e) {
                float a, b;
                unpack2(h2[e][jl >> 1], a, b);
                float hj = (jl & 1) ? b : a;
                unsigned long long pj = pack2(hj, hj);
                ffma2(op[e][0], pj, w01.x);
                ffma2(op[e][1], pj, w01.y);
                ffma2(op[e][2], pj, w23.x);
                ffma2(op[e][3], pj, w23.y);
                ffma2(op[e][4], pj, w45.x);
                ffma2(op[e][5], pj, w45.y);
                ffma2(op[e][6], pj, w67.x);
                ffma2(op[e][7], pj, w67.y);
            }
        }
    }

    // ---- fold + scatter (slot 15 carries the count 1.0) ----
    #pragma unroll
    for (int e = 0; e < 4; ++e) {
        if (!full && (e0 + e >= E)) break;
        float o[16];
        #pragma unroll
        for (int kp = 0; kp < 8; ++kp)
            unpack2(op[e][kp], o[2 * kp], o[2 * kp + 1]);
        o[15] = 1.0f;
        float* dst = &g_x2sum[(size_t)r[e] * 16];
        red4(dst + 0,  o[0],  o[1],  o[2],  o[3]);
        red4(dst + 4,  o[4],  o[5],  o[6],  o[7]);
        red4(dst + 8,  o[8],  o[9],  o[10], o[11]);
        red4(dst + 12, o[12], o[13], o[14], o[15]);
    }
}

// ---------------- graph kernel: per-graph reduce + PARALLEL head ----------
#define SG_GW1 0
#define SG_GB1 (SG_GW1 + 16 * D2)
#define SG_GW2 (SG_GB1 + D2)
#define SG_GB2 (SG_GW2 + D2 * D3)
#define SG_F1W (SG_GB2 + D3)
#define SG_F1B (SG_F1W + D3 * D5)
#define SG_BNG (SG_F1B + D5)
#define SG_BNB (SG_BNG + D5)
#define SG_F2W (SG_BNB + D5)
#define SG_F2B (SG_F2W + D5 * NC)
#define SG_TOTAL (SG_F2B + NC)

__device__ __forceinline__ int lbound(const int* a, int n, int key) {
    int lo = 0, hi = n;
    while (lo < hi) { int m = (lo + hi) >> 1; if (a[m] < key) lo = m + 1; else hi = m; }
    return lo;
}

__global__ void __launch_bounds__(256)
graph_kernel(
    const int* __restrict__ batch,
    const float* __restrict__ u,
    const float* __restrict__ gw1, const float* __restrict__ gb1,
    const float* __restrict__ gw2, const float* __restrict__ gb2,
    const float* __restrict__ fc1w, const float* __restrict__ fc1b,
    const float* __restrict__ bng, const float* __restrict__ bnb,
    const float* __restrict__ fc2w, const float* __restrict__ fc2b,
    float* __restrict__ out, int N)
{
    __shared__ float swt[SG_TOTAL];
    __shared__ float sred[8][30];
    __shared__ int sse[2];
    __shared__ float sin16[16];     // head layer-1 input
    __shared__ float szsum[16];     // relu-sum (readout numerator, node part)
    __shared__ float shg[D2];       // head hidden
    __shared__ float sg[16];        // readout vector
    __shared__ float sh1[D5 + 2];   // fc1+bn+relu
    __shared__ float slse[1];

    int tid = threadIdx.x;
    for (int t = tid; t < 16 * D2; t += blockDim.x) swt[SG_GW1 + t] = gw1[t];
    for (int t = tid; t < D2; t += blockDim.x) swt[SG_GB1 + t] = gb1[t];
    for (int t = tid; t < D2 * D3; t += blockDim.x) swt[SG_GW2 + t] = gw2[t];
    for (int t = tid; t < D3; t += blockDim.x) swt[SG_GB2 + t] = gb2[t];
    for (int t = tid; t < D3 * D5; t += blockDim.x) swt[SG_F1W + t] = fc1w[t];
    for (int t = tid; t < D5; t += blockDim.x) {
        swt[SG_F1B + t] = fc1b[t];
        swt[SG_BNG + t] = bng[t];
        swt[SG_BNB + t] = bnb[t];
    }
    for (int t = tid; t < D5 * NC; t += blockDim.x) swt[SG_F2W + t] = fc2w[t];
    for (int t = tid; t < NC; t += blockDim.x) swt[SG_F2B + t] = fc2b[t];

    int b = blockIdx.x;
    if (tid == 0) {
        sse[0] = lbound(batch, N, b);
        sse[1] = lbound(batch, N, b + 1);
    }
    __syncthreads();
    int s = sse[0], epos = sse[1];
    int nnodes = epos - s;
    float cntf = (float)nnodes;
    float invc = 1.0f / fmaxf(cntf, 1.0f);
    float invg = 1.0f / (cntf + 1.0f);

    // ---- per-thread partials of sum(x2) and sum(relu(x2)) ----
    float acc[30];
    #pragma unroll
    for (int k = 0; k < 30; ++k) acc[k] = 0.0f;

    for (int n = s + tid; n < epos; n += blockDim.x) {
        const float4* p = reinterpret_cast<const float4*>(&g_x2sum[(size_t)n * 16]);
        float4 a0 = p[0], a1 = p[1], a2 = p[2], a3 = p[3];
        float vv[15] = { a0.x, a0.y, a0.z, a0.w, a1.x, a1.y, a1.z, a1.w,
                         a2.x, a2.y, a2.z, a2.w, a3.x, a3.y, a3.z };
        float cnt = a3.w;
        float inv = 1.0f / fmaxf(cnt, 1.0f);
        #pragma unroll
        for (int k = 0; k < 15; ++k) {
            float t = vv[k] * inv;
            acc[k] += t;
            acc[15 + k] += fmaxf(t, 0.0f);
        }
    }

    #pragma unroll
    for (int k = 0; k < 30; ++k) {
        float v = acc[k];
        #pragma unroll
        for (int off = 16; off > 0; off >>= 1)
            v += __shfl_down_sync(0xFFFFFFFF, v, off);
        acc[k] = v;
    }
    int wid = tid >> 5, lid = tid & 31;
    if (lid == 0) {
        #pragma unroll
        for (int k = 0; k < 30; ++k) sred[wid][k] = acc[k];
    }
    __syncthreads();

    // ---- cross-warp fold, in parallel: thread k handles one component ----
    if (tid < 15) {
        float v = 0.0f;
        #pragma unroll
        for (int w = 0; w < 8; ++w) v += sred[w][tid];
        sin16[1 + tid] = v * invc;            // mean(x2) component
    } else if (tid >= 16 && tid < 31) {
        int k = tid - 16;
        float v = 0.0f;
        #pragma unroll
        for (int w = 0; w < 8; ++w) v += sred[w][15 + k];
        szsum[k] = v;                          // sum(relu(x2)) component
    } else if (tid == 15) {
        sin16[0] = u[b];
    }
    __syncthreads();

    // ---- head layer 1 (16 -> 50): thread j computes hg[j] ----
    if (tid < D2) {
        float v = swt[SG_GB1 + tid];
        #pragma unroll
        for (int i = 0; i < 16; ++i)
            v += sin16[i] * swt[SG_GW1 + i * D2 + tid];
        shg[tid] = fmaxf(v, 0.0f);
    }
    __syncthreads();

    // ---- head layer 2 (50 -> 15) + readout g[k]: thread k ----
    if (tid < D3) {
        float v = swt[SG_GB2 + tid];
        #pragma unroll
        for (int j = 0; j < D2; ++j)
            v += shg[j] * swt[SG_GW2 + j * D3 + tid];
        sg[tid] = (szsum[tid] + fmaxf(v, 0.0f)) * invg;
    }
    __syncthreads();

    // ---- fc1 (15 -> 10) + BN(eval) + relu: thread m ----
    if (tid < D5) {
        float v = swt[SG_F1B + tid];
        #pragma unroll
        for (int k = 0; k < D3; ++k)
            v += sg[k] * swt[SG_F1W + k * D5 + tid];
        float rs = rsqrtf(1.0f + 1e-5f);
        sh1[tid] = fmaxf(v * (swt[SG_BNG + tid] * rs) + swt[SG_BNB + tid], 0.0f);
    }
    __syncthreads();

    // ---- fc2 (10 -> 6): thread q computes logit; reuse sg as logits buf ----
    if (tid < NC) {
        float v = swt[SG_F2B + tid];
        #pragma unroll
        for (int m = 0; m < D5; ++m)
            v += sh1[m] * swt[SG_F2W + m * NC + tid];
        sg[tid] = v;
    }
    __syncthreads();

    // ---- log_softmax: thread 0 computes lse; threads q write out ----
    if (tid == 0) {
        float mx = sg[0];
        #pragma unroll
        for (int q = 1; q < NC; ++q) mx = fmaxf(mx, sg[q]);
        float ssum = 0.0f;
        #pragma unroll
        for (int q = 0; q < NC; ++q) ssum += expf(sg[q] - mx);
        slse[0] = mx + logf(ssum);
    }
    __syncthreads();
    if (tid < NC)
        out[b * NC + tid] = sg[tid] - slse[0];
}

// ---------------- launch ----------------
extern "C" void kernel_launch(void* const* d_in, const int* in_sizes, int n_in,
                              void* d_out, int out_size) {
    const float* x     = (const float*)d_in[0];
    const int*   ei    = (const int*)d_in[1];
    const float* ea    = (const float*)d_in[2];
    const float* u     = (const float*)d_in[3];
    const int*   batch = (const int*)d_in[4];
    const float* ew1   = (const float*)d_in[5];
    const float* eb1   = (const float*)d_in[6];
    const float* ew2   = (const float*)d_in[7];
    const float* eb2   = (const float*)d_in[8];
    const float* nw1   = (const float*)d_in[9];
    const float* nb1   = (const float*)d_in[10];
    const float* nw2   = (const float*)d_in[11];
    const float* nb2   = (const float*)d_in[12];
    const float* gw1   = (const float*)d_in[13];
    const float* gb1   = (const float*)d_in[14];
    const float* gw2   = (const float*)d_in[15];
    const float* gb2   = (const float*)d_in[16];
    const float* fc1w  = (const float*)d_in[17];
    const float* fc1b  = (const float*)d_in[18];
    const float* bng   = (const float*)d_in[19];
    const float* bnb   = (const float*)d_in[20];
    const float* fc2w  = (const float*)d_in[21];
    const float* fc2b  = (const float*)d_in[22];
    float* out = (float*)d_out;

    int N = in_sizes[0] / 3;   // nodes
    int E = in_sizes[1] / 2;   // edges
    int B = in_sizes[3];       // graphs

    const int* row = ei;
    const int* col = ei + E;

    // invariant: g_x2sum is zero at entry (module-load init / trailing zero)
    int P = (E + 3) / 4;       // 4 edges per thread
    edge_kernel<<<(P + 127) / 128, 128>>>(x, row, col, ea,
                                          ew1, eb1, ew2, eb2,
                                          nw1, nb1, nw2, nb2, P, E);

    graph_kernel<<<B, 256>>>(batch, u,
                             gw1, gb1, gw2, gb2,
                             fc1w, fc1b, bng, bnb, fc2w, fc2b, out, N);

    // restore the zero invariant for the next replay
    zero_kernel<<<512, 256>>>(N);
}